// round 1
// baseline (speedup 1.0000x reference)
#include <cuda_runtime.h>
#include <cuda_bf16.h>
#include <math.h>

// Problem constants (hardcoded from reference)
#define B_ 4
#define S_ 2048
#define H_ 16
#define D_ 64          // head dim (key and val)
#define DM_ 1024       // model dim
#define M8_ 8192       // B_*S_
#define BH_ 64         // B_*H_
#define SCALE_ 0.125f  // 1/sqrt(64)
#define EPS_ 1e-6f

#define OUT_ELEMS   (M8_ * DM_)                 // 8388608
#define ATTN_ELEMS  ((size_t)BH_ * S_ * S_)     // 268435456

// ---------------- device scratch (allocation-free rule: __device__ globals) -----
__device__ float g_QH[(size_t)BH_ * S_ * D_];   // [B,H,S,D] 32MB
__device__ float g_KH[(size_t)BH_ * S_ * D_];
__device__ float g_VH[(size_t)BH_ * S_ * D_];
__device__ float g_AO[(size_t)M8_ * DM_];       // attention out, [B,S,H*D]
__device__ float g_FC[(size_t)M8_ * DM_];       // fc out + residual
__device__ float g_M[(size_t)BH_ * S_];         // row max
__device__ float g_L[(size_t)BH_ * S_];         // row sumexp

// =================================================================================
// Generic tiled fp32 GEMM: C[M,N] = A[M,K] @ W[N,K]^T  (+resid), optional
// head-major output remap ([B,S,H*D] row/col -> [B,H,S,D]).
// Block 256 threads, 64x64 tile, BK=16, 4x4 per thread.
// =================================================================================
__global__ void gemm_nt_kernel(const float* __restrict__ A, const float* __restrict__ W,
                               float* __restrict__ C, int K,
                               int headmajor, const float* __restrict__ resid) {
    __shared__ float As[64][17];
    __shared__ float Ws[64][17];
    const int tid = threadIdx.x;
    const int tx = tid & 15, ty = tid >> 4;
    const int n0 = blockIdx.x * 64, m0 = blockIdx.y * 64;

    float acc[4][4];
#pragma unroll
    for (int i = 0; i < 4; i++)
#pragma unroll
        for (int j = 0; j < 4; j++) acc[i][j] = 0.f;

    for (int k0 = 0; k0 < K; k0 += 16) {
#pragma unroll
        for (int i = 0; i < 4; i++) {
            int idx = tid + i * 256;
            int r = idx >> 4, c = idx & 15;
            As[r][c] = A[(size_t)(m0 + r) * K + k0 + c];
            Ws[r][c] = W[(size_t)(n0 + r) * K + k0 + c];
        }
        __syncthreads();
#pragma unroll
        for (int kk = 0; kk < 16; kk++) {
            float a[4], b[4];
#pragma unroll
            for (int i = 0; i < 4; i++) a[i] = As[ty * 4 + i][kk];
#pragma unroll
            for (int j = 0; j < 4; j++) b[j] = Ws[tx * 4 + j][kk];
#pragma unroll
            for (int i = 0; i < 4; i++)
#pragma unroll
                for (int j = 0; j < 4; j++) acc[i][j] = fmaf(a[i], b[j], acc[i][j]);
        }
        __syncthreads();
    }

#pragma unroll
    for (int i = 0; i < 4; i++) {
        int row = m0 + ty * 4 + i;
#pragma unroll
        for (int j = 0; j < 4; j++) {
            int col = n0 + tx * 4 + j;
            float v = acc[i][j];
            if (resid) v += resid[(size_t)row * DM_ + col];
            if (headmajor) {
                int b = row >> 11, s = row & (S_ - 1);
                int h = col >> 6, d = col & (D_ - 1);
                C[((((size_t)(b * H_ + h)) * S_) + s) * D_ + d] = v;
            } else {
                C[(size_t)row * DM_ + col] = v;
            }
        }
    }
}

// =================================================================================
// Attention pass A: flash-style online softmax. Block = 64 q rows of one (b,h).
// K/V tiles of 32. Produces AO (normalized PV) + saves row max/sumexp for pass B.
// =================================================================================
__global__ void attn_pass_a_kernel(const float* __restrict__ QH, const float* __restrict__ KH,
                                   const float* __restrict__ VH, float* __restrict__ AO,
                                   float* __restrict__ Mv, float* __restrict__ Lv) {
    const int bh = blockIdx.y;
    const int q0 = blockIdx.x * 64;
    const float* Qp = QH + (size_t)bh * S_ * D_;
    const float* Kp = KH + (size_t)bh * S_ * D_;
    const float* Vp = VH + (size_t)bh * S_ * D_;

    __shared__ float Qs[64][65];
    __shared__ float Ks[32][65];
    __shared__ float Vs[32][65];
    __shared__ float Ss[64][33];
    __shared__ float corr[64], rowm[64], rowl[64];

    const int tid = threadIdx.x;
    // mapping for S compute: 32 row-groups x 8 col-groups
    const int stx = tid & 7, sty = tid >> 3;
    // mapping for O: 16 row-groups x 16 col-groups
    const int otx = tid & 15, oty = tid >> 4;

#pragma unroll
    for (int i = 0; i < 16; i++) {
        int idx = tid + i * 256;
        int r = idx >> 6, c = idx & 63;
        Qs[r][c] = Qp[(size_t)(q0 + r) * D_ + c];
    }
    if (tid < 64) { rowm[tid] = -1e30f; rowl[tid] = 0.f; }

    float O[4][4];
#pragma unroll
    for (int i = 0; i < 4; i++)
#pragma unroll
        for (int j = 0; j < 4; j++) O[i][j] = 0.f;

    __syncthreads();

    for (int kt = 0; kt < S_ / 32; kt++) {
        const int k0 = kt * 32;
#pragma unroll
        for (int i = 0; i < 8; i++) {
            int idx = tid + i * 256;
            int r = idx >> 6, c = idx & 63;
            Ks[r][c] = Kp[(size_t)(k0 + r) * D_ + c];
            Vs[r][c] = Vp[(size_t)(k0 + r) * D_ + c];
        }
        __syncthreads();

        // S = (Q @ K^T) * scale  (each thread: 2 rows x 4 cols)
        float sacc[2][4];
#pragma unroll
        for (int i = 0; i < 2; i++)
#pragma unroll
            for (int j = 0; j < 4; j++) sacc[i][j] = 0.f;
#pragma unroll 8
        for (int kk = 0; kk < 64; kk++) {
            float a0 = Qs[sty * 2 + 0][kk];
            float a1 = Qs[sty * 2 + 1][kk];
#pragma unroll
            for (int j = 0; j < 4; j++) {
                float b = Ks[stx * 4 + j][kk];
                sacc[0][j] = fmaf(a0, b, sacc[0][j]);
                sacc[1][j] = fmaf(a1, b, sacc[1][j]);
            }
        }
#pragma unroll
        for (int i = 0; i < 2; i++)
#pragma unroll
            for (int j = 0; j < 4; j++)
                Ss[sty * 2 + i][stx * 4 + j] = sacc[i][j] * SCALE_;
        __syncthreads();

        // online softmax row update (one thread per q row)
        if (tid < 64) {
            int r = tid;
            float m_old = rowm[r];
            float mx = m_old;
#pragma unroll 8
            for (int j = 0; j < 32; j++) mx = fmaxf(mx, Ss[r][j]);
            float c = __expf(m_old - mx);
            float l = rowl[r] * c;
#pragma unroll 8
            for (int j = 0; j < 32; j++) {
                float p = __expf(Ss[r][j] - mx);
                Ss[r][j] = p;
                l += p;
            }
            rowm[r] = mx; rowl[r] = l; corr[r] = c;
        }
        __syncthreads();

        // O = O*corr + P @ V  (each thread: 4 rows x 4 cols)
#pragma unroll
        for (int i = 0; i < 4; i++) {
            float cr = corr[oty * 4 + i];
#pragma unroll
            for (int j = 0; j < 4; j++) O[i][j] *= cr;
        }
#pragma unroll 4
        for (int jj = 0; jj < 32; jj++) {
            float b[4];
#pragma unroll
            for (int j = 0; j < 4; j++) b[j] = Vs[jj][otx * 4 + j];
#pragma unroll
            for (int i = 0; i < 4; i++) {
                float p = Ss[oty * 4 + i][jj];
#pragma unroll
                for (int j = 0; j < 4; j++) O[i][j] = fmaf(p, b[j], O[i][j]);
            }
        }
        __syncthreads();
    }

    // epilogue: AO[b][s][h*64+d] = O/l
    const int b = bh >> 4, h = bh & 15;
#pragma unroll
    for (int i = 0; i < 4; i++) {
        int r = oty * 4 + i;
        float invl = 1.f / rowl[r];
        size_t base = ((size_t)b * S_ + (q0 + r)) * DM_ + h * D_;
#pragma unroll
        for (int j = 0; j < 4; j++)
            AO[base + otx * 4 + j] = O[i][j] * invl;
    }
    if (tid < 64) {
        Mv[(size_t)bh * S_ + q0 + tid] = rowm[tid];
        Lv[(size_t)bh * S_ + q0 + tid] = rowl[tid];
    }
}

// =================================================================================
// Attention pass B: recompute scores, write normalized attn = exp(s*scale - m)/l.
// Block: 64 q x 64 k tile of one (b,h).
// =================================================================================
__global__ void attn_pass_b_kernel(const float* __restrict__ QH, const float* __restrict__ KH,
                                   const float* __restrict__ Mv, const float* __restrict__ Lv,
                                   float* __restrict__ attn) {
    const int bh = blockIdx.z;
    const int q0 = blockIdx.y * 64;
    const int k0 = blockIdx.x * 64;
    const float* Qp = QH + (size_t)bh * S_ * D_;
    const float* Kp = KH + (size_t)bh * S_ * D_;

    __shared__ float Qs[64][65];
    __shared__ float Ks[64][65];
    __shared__ float m_s[64], invl_s[64];

    const int tid = threadIdx.x;
    const int tx = tid & 15, ty = tid >> 4;

#pragma unroll
    for (int i = 0; i < 16; i++) {
        int idx = tid + i * 256;
        int r = idx >> 6, c = idx & 63;
        Qs[r][c] = Qp[(size_t)(q0 + r) * D_ + c];
        Ks[r][c] = Kp[(size_t)(k0 + r) * D_ + c];
    }
    if (tid < 64) {
        m_s[tid] = Mv[(size_t)bh * S_ + q0 + tid];
        invl_s[tid] = 1.f / Lv[(size_t)bh * S_ + q0 + tid];
    }
    __syncthreads();

    float acc[4][4];
#pragma unroll
    for (int i = 0; i < 4; i++)
#pragma unroll
        for (int j = 0; j < 4; j++) acc[i][j] = 0.f;

#pragma unroll 8
    for (int kk = 0; kk < 64; kk++) {
        float a[4], b[4];
#pragma unroll
        for (int i = 0; i < 4; i++) a[i] = Qs[ty * 4 + i][kk];
#pragma unroll
        for (int j = 0; j < 4; j++) b[j] = Ks[tx * 4 + j][kk];
#pragma unroll
        for (int i = 0; i < 4; i++)
#pragma unroll
            for (int j = 0; j < 4; j++) acc[i][j] = fmaf(a[i], b[j], acc[i][j]);
    }

#pragma unroll
    for (int i = 0; i < 4; i++) {
        int r = ty * 4 + i;
        float m = m_s[r], invl = invl_s[r];
        float4 v;
        v.x = __expf(acc[i][0] * SCALE_ - m) * invl;
        v.y = __expf(acc[i][1] * SCALE_ - m) * invl;
        v.z = __expf(acc[i][2] * SCALE_ - m) * invl;
        v.w = __expf(acc[i][3] * SCALE_ - m) * invl;
        size_t off = ((size_t)bh * S_ + (q0 + r)) * S_ + k0 + tx * 4;
        *reinterpret_cast<float4*>(attn + off) = v;
    }
}

// =================================================================================
// LayerNorm over last dim (1024). One block per row; FC already has residual added.
// =================================================================================
__global__ void ln_kernel(const float* __restrict__ FC, const float* __restrict__ gamma,
                          const float* __restrict__ beta, float* __restrict__ out) {
    __shared__ float sbuf[32];
    const int row = blockIdx.x;
    const int tid = threadIdx.x;
    const float* x = FC + (size_t)row * DM_;

    float v[4];
    float s = 0.f;
#pragma unroll
    for (int i = 0; i < 4; i++) { v[i] = x[tid + i * 256]; s += v[i]; }

    // block sum
    {
        int lane = tid & 31, wid = tid >> 5;
        for (int o = 16; o > 0; o >>= 1) s += __shfl_down_sync(0xffffffffu, s, o);
        if (lane == 0) sbuf[wid] = s;
        __syncthreads();
        if (wid == 0) {
            float t = (lane < 8) ? sbuf[lane] : 0.f;
            for (int o = 4; o > 0; o >>= 1) t += __shfl_down_sync(0xffffffffu, t, o);
            if (lane == 0) sbuf[0] = t;
        }
        __syncthreads();
    }
    float mu = sbuf[0] * (1.f / DM_);
    __syncthreads();

    float s2 = 0.f;
#pragma unroll
    for (int i = 0; i < 4; i++) { float d = v[i] - mu; s2 += d * d; }
    {
        int lane = tid & 31, wid = tid >> 5;
        for (int o = 16; o > 0; o >>= 1) s2 += __shfl_down_sync(0xffffffffu, s2, o);
        if (lane == 0) sbuf[wid] = s2;
        __syncthreads();
        if (wid == 0) {
            float t = (lane < 8) ? sbuf[lane] : 0.f;
            for (int o = 4; o > 0; o >>= 1) t += __shfl_down_sync(0xffffffffu, t, o);
            if (lane == 0) sbuf[0] = t;
        }
        __syncthreads();
    }
    float inv = rsqrtf(sbuf[0] * (1.f / DM_) + EPS_);

#pragma unroll
    for (int i = 0; i < 4; i++) {
        int c = tid + i * 256;
        out[(size_t)row * DM_ + c] = (v[i] - mu) * inv * gamma[c] + beta[c];
    }
}

// =================================================================================
// Launch
// =================================================================================
extern "C" void kernel_launch(void* const* d_in, const int* in_sizes, int n_in,
                              void* d_out, int out_size) {
    const float* q     = (const float*)d_in[0];
    const float* k     = (const float*)d_in[1];
    const float* v     = (const float*)d_in[2];
    const float* w_q   = (const float*)d_in[3];
    const float* w_k   = (const float*)d_in[4];
    const float* w_v   = (const float*)d_in[5];
    const float* w_fc  = (const float*)d_in[6];
    const float* gamma = (const float*)d_in[7];
    const float* beta  = (const float*)d_in[8];

    float* out  = (float*)d_out;
    float* attn = out + OUT_ELEMS;   // outputs concatenated: (out, attn)

    void *pQH, *pKH, *pVH, *pAO, *pFC, *pM, *pL;
    cudaGetSymbolAddress(&pQH, g_QH);
    cudaGetSymbolAddress(&pKH, g_KH);
    cudaGetSymbolAddress(&pVH, g_VH);
    cudaGetSymbolAddress(&pAO, g_AO);
    cudaGetSymbolAddress(&pFC, g_FC);
    cudaGetSymbolAddress(&pM, g_M);
    cudaGetSymbolAddress(&pL, g_L);
    float* QH = (float*)pQH; float* KH = (float*)pKH; float* VH = (float*)pVH;
    float* AO = (float*)pAO; float* FC = (float*)pFC;
    float* Mv = (float*)pM;  float* Lv = (float*)pL;

    dim3 gemm_grid(DM_ / 64, M8_ / 64);   // (16, 128)

    // projections -> head-major [B,H,S,D]
    gemm_nt_kernel<<<gemm_grid, 256>>>(q, w_q, QH, DM_, 1, nullptr);
    gemm_nt_kernel<<<gemm_grid, 256>>>(k, w_k, KH, DM_, 1, nullptr);
    gemm_nt_kernel<<<gemm_grid, 256>>>(v, w_v, VH, DM_, 1, nullptr);

    // pass A: flash attention -> AO + (m, l)
    attn_pass_a_kernel<<<dim3(S_ / 64, BH_), 256>>>(QH, KH, VH, AO, Mv, Lv);

    // pass B: write normalized attention probabilities (second output)
    if ((size_t)out_size >= OUT_ELEMS + ATTN_ELEMS) {
        attn_pass_b_kernel<<<dim3(S_ / 64, S_ / 64, BH_), 256>>>(QH, KH, Mv, Lv, attn);
    }

    // fc + residual
    gemm_nt_kernel<<<gemm_grid, 256>>>(AO, w_fc, FC, DM_, 0, q);

    // layernorm -> out (first output)
    ln_kernel<<<M8_, 256>>>(FC, gamma, beta, out);
}

// round 2
// speedup vs baseline: 3.0079x; 3.0079x over previous
#include <cuda_runtime.h>
#include <cuda_bf16.h>
#include <math.h>
#include <stdint.h>

// Problem constants
#define B_ 4
#define S_ 2048
#define H_ 16
#define D_ 64
#define DM_ 1024
#define M8_ 8192
#define BH_ 64
#define SCALE_ 0.125f
#define EPS_ 1e-6f

#define OUT_ELEMS   (M8_ * DM_)
#define ATTN_ELEMS  ((size_t)BH_ * S_ * S_)

// ---------------- device scratch -----------------------------------------------
__device__ float g_QH[(size_t)BH_ * S_ * D_];   // [B,H,S,D]
__device__ float g_KH[(size_t)BH_ * S_ * D_];
__device__ float g_VH[(size_t)BH_ * S_ * D_];
__device__ float g_AO[(size_t)M8_ * DM_];       // [B,S,H*D]
__device__ float g_FC[(size_t)M8_ * DM_];
__device__ float g_M[(size_t)BH_ * S_];
__device__ float g_L[(size_t)BH_ * S_];

// ---------------- tf32 mma helpers ----------------------------------------------
__device__ __forceinline__ uint32_t f2tf32(float x) {
    uint32_t u;
    asm("cvt.rna.tf32.f32 %0, %1;" : "=r"(u) : "f"(x));
    return u;
}

__device__ __forceinline__ void mma8(float* c, const uint32_t* a, const uint32_t* b) {
    asm volatile(
        "mma.sync.aligned.m16n8k8.row.col.f32.tf32.tf32.f32 "
        "{%0,%1,%2,%3}, {%4,%5,%6,%7}, {%8,%9}, {%0,%1,%2,%3};"
        : "+f"(c[0]), "+f"(c[1]), "+f"(c[2]), "+f"(c[3])
        : "r"(a[0]), "r"(a[1]), "r"(a[2]), "r"(a[3]), "r"(b[0]), "r"(b[1]));
}

// =================================================================================
// tf32 GEMM: C[M,N] = A[M,K] @ W[N,K]^T (+resid). N row stride = DM_ (1024).
// 128x128 tile, BK=32, 256 threads, 8 warps (4m x 2n), warp tile 32x64.
// headmajor: remap [B,S,H*D] -> [B,H,S,D].
// =================================================================================
__global__ __launch_bounds__(256) void gemm_tf32_kernel(
    const float* __restrict__ A, const float* __restrict__ W, float* __restrict__ C,
    int K, int headmajor, const float* __restrict__ resid) {
    __shared__ uint32_t As[128][36];
    __shared__ uint32_t Ws[128][36];

    const int tid = threadIdx.x;
    const int lane = tid & 31, warp = tid >> 5;
    const int wm = warp >> 1, wn = warp & 1;
    const int rm = wm * 32, cn = wn * 64;
    const int m0 = blockIdx.y * 128, n0 = blockIdx.x * 128;

    float acc[2][8][4];
#pragma unroll
    for (int mt = 0; mt < 2; mt++)
#pragma unroll
        for (int nt = 0; nt < 8; nt++)
#pragma unroll
            for (int i = 0; i < 4; i++) acc[mt][nt][i] = 0.f;

    for (int k0 = 0; k0 < K; k0 += 32) {
#pragma unroll
        for (int p = 0; p < 4; p++) {
            int idx = tid + p * 256;           // 1024 float4 slots
            int r = idx >> 3, c4 = (idx & 7) * 4;
            float4 av = *(const float4*)(A + (size_t)(m0 + r) * K + k0 + c4);
            float4 wv = *(const float4*)(W + (size_t)(n0 + r) * K + k0 + c4);
            *(uint4*)&As[r][c4] = make_uint4(f2tf32(av.x), f2tf32(av.y), f2tf32(av.z), f2tf32(av.w));
            *(uint4*)&Ws[r][c4] = make_uint4(f2tf32(wv.x), f2tf32(wv.y), f2tf32(wv.z), f2tf32(wv.w));
        }
        __syncthreads();

#pragma unroll
        for (int kk = 0; kk < 4; kk++) {
            const int c0 = kk * 8 + (lane & 3);
            uint32_t a[2][4];
#pragma unroll
            for (int mt = 0; mt < 2; mt++) {
                int r0 = rm + mt * 16 + (lane >> 2);
                a[mt][0] = As[r0][c0];
                a[mt][1] = As[r0 + 8][c0];
                a[mt][2] = As[r0][c0 + 4];
                a[mt][3] = As[r0 + 8][c0 + 4];
            }
            uint32_t b[8][2];
#pragma unroll
            for (int nt = 0; nt < 8; nt++) {
                int rb = cn + nt * 8 + (lane >> 2);
                b[nt][0] = Ws[rb][c0];
                b[nt][1] = Ws[rb][c0 + 4];
            }
#pragma unroll
            for (int mt = 0; mt < 2; mt++)
#pragma unroll
                for (int nt = 0; nt < 8; nt++) mma8(acc[mt][nt], a[mt], b[nt]);
        }
        __syncthreads();
    }

    // epilogue
#pragma unroll
    for (int mt = 0; mt < 2; mt++) {
#pragma unroll
        for (int nt = 0; nt < 8; nt++) {
#pragma unroll
            for (int half = 0; half < 2; half++) {
                int row = m0 + rm + mt * 16 + (lane >> 2) + half * 8;
                int col = n0 + cn + nt * 8 + 2 * (lane & 3);
                float v0 = acc[mt][nt][half * 2 + 0];
                float v1 = acc[mt][nt][half * 2 + 1];
                if (resid) {
                    v0 += resid[(size_t)row * DM_ + col];
                    v1 += resid[(size_t)row * DM_ + col + 1];
                }
                if (headmajor) {
                    int b = row >> 11, s = row & (S_ - 1);
                    int h = col >> 6, d = col & (D_ - 1);
                    float2* p = (float2*)&C[((((size_t)(b * H_ + h)) * S_) + s) * D_ + d];
                    *p = make_float2(v0, v1);
                } else {
                    float2* p = (float2*)&C[(size_t)row * DM_ + col];
                    *p = make_float2(v0, v1);
                }
            }
        }
    }
}

// =================================================================================
// Attention pass A (flash): block = 128 q rows of one (b,h), k tiles of 64.
// mma for QK^T and PV; softmax via smem. Saves rowmax/rowsum for pass B.
// =================================================================================
__global__ __launch_bounds__(256) void attn_a_tf32_kernel(
    const float* __restrict__ QH, const float* __restrict__ KH,
    const float* __restrict__ VH, float* __restrict__ AO,
    float* __restrict__ Mv, float* __restrict__ Lv) {
    extern __shared__ uint32_t sm[];
    uint32_t* Qs = sm;                    // [128][68] tf32
    uint32_t* Ks = Qs + 128 * 68;         // [64][68] tf32
    uint32_t* Vt = Ks + 64 * 68;          // [64 d][68 key] tf32
    uint32_t* Ss = Vt + 64 * 68;          // [128][68] raw f32 scores, then tf32 P
    float* rowm = (float*)(Ss + 128 * 68);
    float* rowl = rowm + 128;
    float* corr = rowl + 128;

    const int tid = threadIdx.x;
    const int lane = tid & 31, warp = tid >> 5;
    const int wm = warp >> 1, wn = warp & 1;
    const int rm = wm * 32;
    const int bh = blockIdx.y;
    const int q0 = blockIdx.x * 128;

    const float* Qp = QH + (size_t)bh * S_ * D_;
    const float* Kp = KH + (size_t)bh * S_ * D_;
    const float* Vp = VH + (size_t)bh * S_ * D_;

    // load Q tile
#pragma unroll
    for (int p = 0; p < 8; p++) {
        int idx = tid + p * 256;           // 2048 f4 slots
        int r = idx >> 4, c4 = (idx & 15) * 4;
        float4 v = *(const float4*)(Qp + (size_t)(q0 + r) * D_ + c4);
        *(uint4*)&Qs[r * 68 + c4] = make_uint4(f2tf32(v.x), f2tf32(v.y), f2tf32(v.z), f2tf32(v.w));
    }
    if (tid < 128) { rowm[tid] = -1e30f; rowl[tid] = 0.f; }

    float o[2][4][4];
#pragma unroll
    for (int mt = 0; mt < 2; mt++)
#pragma unroll
        for (int nt = 0; nt < 4; nt++)
#pragma unroll
            for (int i = 0; i < 4; i++) o[mt][nt][i] = 0.f;

    __syncthreads();

    for (int kt = 0; kt < S_ / 64; kt++) {
        const int k0 = kt * 64;
        // load K tile + V tile (transposed)
#pragma unroll
        for (int p = 0; p < 4; p++) {
            int idx = tid + p * 256;       // 1024 f4 slots
            int r = idx >> 4, c4 = (idx & 15) * 4;
            float4 kv = *(const float4*)(Kp + (size_t)(k0 + r) * D_ + c4);
            *(uint4*)&Ks[r * 68 + c4] = make_uint4(f2tf32(kv.x), f2tf32(kv.y), f2tf32(kv.z), f2tf32(kv.w));
            float4 vv = *(const float4*)(Vp + (size_t)(k0 + r) * D_ + c4);
            Vt[(c4 + 0) * 68 + r] = f2tf32(vv.x);
            Vt[(c4 + 1) * 68 + r] = f2tf32(vv.y);
            Vt[(c4 + 2) * 68 + r] = f2tf32(vv.z);
            Vt[(c4 + 3) * 68 + r] = f2tf32(vv.w);
        }
        __syncthreads();

        // S = Q @ K^T (warp tile 32x32): mt x nt = 2 x 4
        {
            float sacc[2][4][4];
#pragma unroll
            for (int mt = 0; mt < 2; mt++)
#pragma unroll
                for (int nt = 0; nt < 4; nt++)
#pragma unroll
                    for (int i = 0; i < 4; i++) sacc[mt][nt][i] = 0.f;

            const int cns = wn * 32;
#pragma unroll
            for (int kk = 0; kk < 8; kk++) {
                const int c0 = kk * 8 + (lane & 3);
                uint32_t a[2][4];
#pragma unroll
                for (int mt = 0; mt < 2; mt++) {
                    int r0 = rm + mt * 16 + (lane >> 2);
                    a[mt][0] = Qs[r0 * 68 + c0];
                    a[mt][1] = Qs[(r0 + 8) * 68 + c0];
                    a[mt][2] = Qs[r0 * 68 + c0 + 4];
                    a[mt][3] = Qs[(r0 + 8) * 68 + c0 + 4];
                }
                uint32_t b[4][2];
#pragma unroll
                for (int nt = 0; nt < 4; nt++) {
                    int rb = cns + nt * 8 + (lane >> 2);
                    b[nt][0] = Ks[rb * 68 + c0];
                    b[nt][1] = Ks[rb * 68 + c0 + 4];
                }
#pragma unroll
                for (int mt = 0; mt < 2; mt++)
#pragma unroll
                    for (int nt = 0; nt < 4; nt++) mma8(sacc[mt][nt], a[mt], b[nt]);
            }
            // store scaled scores (fp32 bits) to Ss
#pragma unroll
            for (int mt = 0; mt < 2; mt++)
#pragma unroll
                for (int nt = 0; nt < 4; nt++)
#pragma unroll
                    for (int half = 0; half < 2; half++) {
                        int r0 = rm + mt * 16 + (lane >> 2) + half * 8;
                        int c = cns + nt * 8 + 2 * (lane & 3);
                        float2 sv = make_float2(sacc[mt][nt][half * 2] * SCALE_,
                                                sacc[mt][nt][half * 2 + 1] * SCALE_);
                        *(float2*)&Ss[r0 * 68 + c] = sv;
                    }
        }
        __syncthreads();

        // online softmax: 2 threads per row, 32 cols each
        {
            int r = tid >> 1, half = tid & 1;
            int cbase = half * 32;
            float pmax = -1e30f;
#pragma unroll 8
            for (int j = 0; j < 32; j++)
                pmax = fmaxf(pmax, __uint_as_float(Ss[r * 68 + cbase + j]));
            float other = __shfl_xor_sync(0xffffffffu, pmax, 1);
            float tmax = fmaxf(pmax, other);
            float m_old = rowm[r];
            float m_new = fmaxf(m_old, tmax);
            float cc = __expf(m_old - m_new);
            float psum = 0.f;
#pragma unroll 8
            for (int j = 0; j < 32; j++) {
                float p = __expf(__uint_as_float(Ss[r * 68 + cbase + j]) - m_new);
                Ss[r * 68 + cbase + j] = f2tf32(p);
                psum += p;
            }
            psum += __shfl_xor_sync(0xffffffffu, psum, 1);
            if (half == 0) {
                rowl[r] = rowl[r] * cc + psum;
                rowm[r] = m_new;
                corr[r] = cc;
            }
        }
        __syncthreads();

        // O = O*corr + P @ V  (warp tile 32x32 over d)
        {
#pragma unroll
            for (int mt = 0; mt < 2; mt++) {
                float c0_ = corr[rm + mt * 16 + (lane >> 2)];
                float c1_ = corr[rm + mt * 16 + 8 + (lane >> 2)];
#pragma unroll
                for (int nt = 0; nt < 4; nt++) {
                    o[mt][nt][0] *= c0_; o[mt][nt][1] *= c0_;
                    o[mt][nt][2] *= c1_; o[mt][nt][3] *= c1_;
                }
            }
            const int cnd = wn * 32;
#pragma unroll
            for (int kk = 0; kk < 8; kk++) {
                const int c0 = kk * 8 + (lane & 3);
                uint32_t a[2][4];
#pragma unroll
                for (int mt = 0; mt < 2; mt++) {
                    int r0 = rm + mt * 16 + (lane >> 2);
                    a[mt][0] = Ss[r0 * 68 + c0];
                    a[mt][1] = Ss[(r0 + 8) * 68 + c0];
                    a[mt][2] = Ss[r0 * 68 + c0 + 4];
                    a[mt][3] = Ss[(r0 + 8) * 68 + c0 + 4];
                }
                uint32_t b[4][2];
#pragma unroll
                for (int nt = 0; nt < 4; nt++) {
                    int rb = cnd + nt * 8 + (lane >> 2);
                    b[nt][0] = Vt[rb * 68 + c0];
                    b[nt][1] = Vt[rb * 68 + c0 + 4];
                }
#pragma unroll
                for (int mt = 0; mt < 2; mt++)
#pragma unroll
                    for (int nt = 0; nt < 4; nt++) mma8(o[mt][nt], a[mt], b[nt]);
            }
        }
        __syncthreads();
    }

    // epilogue
    const int b = bh >> 4, h = bh & 15;
#pragma unroll
    for (int mt = 0; mt < 2; mt++) {
        int r0 = rm + mt * 16 + (lane >> 2);
        float il0 = 1.f / rowl[r0];
        float il1 = 1.f / rowl[r0 + 8];
#pragma unroll
        for (int nt = 0; nt < 4; nt++) {
            int c = wn * 32 + nt * 8 + 2 * (lane & 3);
            size_t base0 = ((size_t)b * S_ + (q0 + r0)) * DM_ + h * D_ + c;
            size_t base1 = ((size_t)b * S_ + (q0 + r0 + 8)) * DM_ + h * D_ + c;
            *(float2*)&AO[base0] = make_float2(o[mt][nt][0] * il0, o[mt][nt][1] * il0);
            *(float2*)&AO[base1] = make_float2(o[mt][nt][2] * il1, o[mt][nt][3] * il1);
        }
    }
    if (tid < 128) {
        Mv[(size_t)bh * S_ + q0 + tid] = rowm[tid];
        Lv[(size_t)bh * S_ + q0 + tid] = rowl[tid];
    }
}

// =================================================================================
// Attention pass B: recompute scores via mma, write attn = exp(s - m)/l.
// Block: 128 q x 128 k of one (b,h).
// =================================================================================
__global__ __launch_bounds__(256) void attn_b_tf32_kernel(
    const float* __restrict__ QH, const float* __restrict__ KH,
    const float* __restrict__ Mv, const float* __restrict__ Lv,
    float* __restrict__ attn) {
    extern __shared__ uint32_t sm[];
    uint32_t* Qs = sm;               // [128][68]
    uint32_t* Ks = Qs + 128 * 68;    // [128][68]
    float* fm = (float*)(Ks + 128 * 68);
    float* fl = fm + 128;

    const int tid = threadIdx.x;
    const int lane = tid & 31, warp = tid >> 5;
    const int wm = warp >> 1, wn = warp & 1;
    const int rm = wm * 32, cn = wn * 64;
    const int bh = blockIdx.z;
    const int q0 = blockIdx.y * 128;
    const int k0 = blockIdx.x * 128;

    const float* Qp = QH + (size_t)bh * S_ * D_;
    const float* Kp = KH + (size_t)bh * S_ * D_;

#pragma unroll
    for (int p = 0; p < 8; p++) {
        int idx = tid + p * 256;
        int r = idx >> 4, c4 = (idx & 15) * 4;
        float4 qv = *(const float4*)(Qp + (size_t)(q0 + r) * D_ + c4);
        float4 kv = *(const float4*)(Kp + (size_t)(k0 + r) * D_ + c4);
        *(uint4*)&Qs[r * 68 + c4] = make_uint4(f2tf32(qv.x), f2tf32(qv.y), f2tf32(qv.z), f2tf32(qv.w));
        *(uint4*)&Ks[r * 68 + c4] = make_uint4(f2tf32(kv.x), f2tf32(kv.y), f2tf32(kv.z), f2tf32(kv.w));
    }
    if (tid < 128) {
        fm[tid] = Mv[(size_t)bh * S_ + q0 + tid];
        fl[tid] = 1.f / Lv[(size_t)bh * S_ + q0 + tid];
    }
    __syncthreads();

    float acc[2][8][4];
#pragma unroll
    for (int mt = 0; mt < 2; mt++)
#pragma unroll
        for (int nt = 0; nt < 8; nt++)
#pragma unroll
            for (int i = 0; i < 4; i++) acc[mt][nt][i] = 0.f;

#pragma unroll
    for (int kk = 0; kk < 8; kk++) {
        const int c0 = kk * 8 + (lane & 3);
        uint32_t a[2][4];
#pragma unroll
        for (int mt = 0; mt < 2; mt++) {
            int r0 = rm + mt * 16 + (lane >> 2);
            a[mt][0] = Qs[r0 * 68 + c0];
            a[mt][1] = Qs[(r0 + 8) * 68 + c0];
            a[mt][2] = Qs[r0 * 68 + c0 + 4];
            a[mt][3] = Qs[(r0 + 8) * 68 + c0 + 4];
        }
        uint32_t b[8][2];
#pragma unroll
        for (int nt = 0; nt < 8; nt++) {
            int rb = cn + nt * 8 + (lane >> 2);
            b[nt][0] = Ks[rb * 68 + c0];
            b[nt][1] = Ks[rb * 68 + c0 + 4];
        }
#pragma unroll
        for (int mt = 0; mt < 2; mt++)
#pragma unroll
            for (int nt = 0; nt < 8; nt++) mma8(acc[mt][nt], a[mt], b[nt]);
    }

    // epilogue: exp + normalize + store
#pragma unroll
    for (int mt = 0; mt < 2; mt++) {
#pragma unroll
        for (int half = 0; half < 2; half++) {
            int r0 = rm + mt * 16 + (lane >> 2) + half * 8;
            float m = fm[r0], il = fl[r0];
            size_t rowbase = ((size_t)bh * S_ + (q0 + r0)) * S_ + k0;
#pragma unroll
            for (int nt = 0; nt < 8; nt++) {
                int c = cn + nt * 8 + 2 * (lane & 3);
                float2 v;
                v.x = __expf(acc[mt][nt][half * 2 + 0] * SCALE_ - m) * il;
                v.y = __expf(acc[mt][nt][half * 2 + 1] * SCALE_ - m) * il;
                *(float2*)&attn[rowbase + c] = v;
            }
        }
    }
}

// =================================================================================
// LayerNorm over last dim (1024).
// =================================================================================
__global__ void ln_kernel(const float* __restrict__ FC, const float* __restrict__ gamma,
                          const float* __restrict__ beta, float* __restrict__ out) {
    __shared__ float sbuf[32];
    const int row = blockIdx.x;
    const int tid = threadIdx.x;
    const float* x = FC + (size_t)row * DM_;

    float v[4];
    float s = 0.f;
#pragma unroll
    for (int i = 0; i < 4; i++) { v[i] = x[tid + i * 256]; s += v[i]; }
    {
        int lane = tid & 31, wid = tid >> 5;
        for (int o = 16; o > 0; o >>= 1) s += __shfl_down_sync(0xffffffffu, s, o);
        if (lane == 0) sbuf[wid] = s;
        __syncthreads();
        if (wid == 0) {
            float t = (lane < 8) ? sbuf[lane] : 0.f;
            for (int o = 4; o > 0; o >>= 1) t += __shfl_down_sync(0xffffffffu, t, o);
            if (lane == 0) sbuf[0] = t;
        }
        __syncthreads();
    }
    float mu = sbuf[0] * (1.f / DM_);
    __syncthreads();

    float s2 = 0.f;
#pragma unroll
    for (int i = 0; i < 4; i++) { float d = v[i] - mu; s2 += d * d; }
    {
        int lane = tid & 31, wid = tid >> 5;
        for (int o = 16; o > 0; o >>= 1) s2 += __shfl_down_sync(0xffffffffu, s2, o);
        if (lane == 0) sbuf[wid] = s2;
        __syncthreads();
        if (wid == 0) {
            float t = (lane < 8) ? sbuf[lane] : 0.f;
            for (int o = 4; o > 0; o >>= 1) t += __shfl_down_sync(0xffffffffu, t, o);
            if (lane == 0) sbuf[0] = t;
        }
        __syncthreads();
    }
    float inv = rsqrtf(sbuf[0] * (1.f / DM_) + EPS_);

#pragma unroll
    for (int i = 0; i < 4; i++) {
        int c = tid + i * 256;
        out[(size_t)row * DM_ + c] = (v[i] - mu) * inv * gamma[c] + beta[c];
    }
}

// =================================================================================
// Launch
// =================================================================================
#define SMEM_A_BYTES ((128*68 + 64*68 + 64*68 + 128*68 + 3*128) * 4)
#define SMEM_B_BYTES ((128*68 + 128*68 + 2*128) * 4)

extern "C" void kernel_launch(void* const* d_in, const int* in_sizes, int n_in,
                              void* d_out, int out_size) {
    const float* q     = (const float*)d_in[0];
    const float* k     = (const float*)d_in[1];
    const float* v     = (const float*)d_in[2];
    const float* w_q   = (const float*)d_in[3];
    const float* w_k   = (const float*)d_in[4];
    const float* w_v   = (const float*)d_in[5];
    const float* w_fc  = (const float*)d_in[6];
    const float* gamma = (const float*)d_in[7];
    const float* beta  = (const float*)d_in[8];

    float* out  = (float*)d_out;
    float* attn = out + OUT_ELEMS;

    void *pQH, *pKH, *pVH, *pAO, *pFC, *pM, *pL;
    cudaGetSymbolAddress(&pQH, g_QH);
    cudaGetSymbolAddress(&pKH, g_KH);
    cudaGetSymbolAddress(&pVH, g_VH);
    cudaGetSymbolAddress(&pAO, g_AO);
    cudaGetSymbolAddress(&pFC, g_FC);
    cudaGetSymbolAddress(&pM, g_M);
    cudaGetSymbolAddress(&pL, g_L);
    float* QH = (float*)pQH; float* KH = (float*)pKH; float* VH = (float*)pVH;
    float* AO = (float*)pAO; float* FC = (float*)pFC;
    float* Mv = (float*)pM;  float* Lv = (float*)pL;

    cudaFuncSetAttribute(attn_a_tf32_kernel, cudaFuncAttributeMaxDynamicSharedMemorySize, SMEM_A_BYTES);
    cudaFuncSetAttribute(attn_b_tf32_kernel, cudaFuncAttributeMaxDynamicSharedMemorySize, SMEM_B_BYTES);

    dim3 gemm_grid(DM_ / 128, M8_ / 128);   // (8, 64)

    // projections -> head-major [B,H,S,D]
    gemm_tf32_kernel<<<gemm_grid, 256>>>(q, w_q, QH, DM_, 1, nullptr);
    gemm_tf32_kernel<<<gemm_grid, 256>>>(k, w_k, KH, DM_, 1, nullptr);
    gemm_tf32_kernel<<<gemm_grid, 256>>>(v, w_v, VH, DM_, 1, nullptr);

    // pass A: flash attention -> AO + (m, l)
    attn_a_tf32_kernel<<<dim3(S_ / 128, BH_), 256, SMEM_A_BYTES>>>(QH, KH, VH, AO, Mv, Lv);

    // pass B: normalized attention probabilities (second output)
    if ((size_t)out_size >= OUT_ELEMS + ATTN_ELEMS) {
        attn_b_tf32_kernel<<<dim3(S_ / 128, S_ / 128, BH_), 256, SMEM_B_BYTES>>>(QH, KH, Mv, Lv, attn);
    }

    // fc + residual
    gemm_tf32_kernel<<<gemm_grid, 256>>>(AO, w_fc, FC, DM_, 0, q);

    // layernorm
    ln_kernel<<<M8_, 256>>>(FC, gamma, beta, out);
}

// round 4
// speedup vs baseline: 3.1725x; 1.0548x over previous
#include <cuda_runtime.h>
#include <cuda_bf16.h>
#include <math.h>
#include <stdint.h>

// Problem constants
#define B_ 4
#define S_ 2048
#define H_ 16
#define D_ 64
#define DM_ 1024
#define M8_ 8192
#define BH_ 64
#define SCALE_ 0.125f
#define EPS_ 1e-6f

#define OUT_ELEMS   (M8_ * DM_)
#define ATTN_ELEMS  ((size_t)BH_ * S_ * S_)

// ---------------- device scratch -----------------------------------------------
__device__ float g_QH[(size_t)BH_ * S_ * D_];   // [B,H,S,D]
__device__ float g_KH[(size_t)BH_ * S_ * D_];
__device__ float g_VH[(size_t)BH_ * S_ * D_];
__device__ float g_AO[(size_t)M8_ * DM_];       // [B,S,H*D]
__device__ float g_FC[(size_t)M8_ * DM_];
__device__ float g_M[(size_t)BH_ * S_];
__device__ float g_L[(size_t)BH_ * S_];

// ---------------- tf32 mma helpers ----------------------------------------------
__device__ __forceinline__ uint32_t f2tf32(float x) {
    uint32_t u;
    asm("cvt.rna.tf32.f32 %0, %1;" : "=r"(u) : "f"(x));
    return u;
}

__device__ __forceinline__ void mma8(float* c, const uint32_t* a, const uint32_t* b) {
    asm volatile(
        "mma.sync.aligned.m16n8k8.row.col.f32.tf32.tf32.f32 "
        "{%0,%1,%2,%3}, {%4,%5,%6,%7}, {%8,%9}, {%0,%1,%2,%3};"
        : "+f"(c[0]), "+f"(c[1]), "+f"(c[2]), "+f"(c[3])
        : "r"(a[0]), "r"(a[1]), "r"(a[2]), "r"(a[3]), "r"(b[0]), "r"(b[1]));
}

// =================================================================================
// tf32 GEMM: C[M,N] = A[M,K] @ W[N,K]^T (+resid). 128x128 tile, BK=32, 256 thr.
// =================================================================================
__global__ __launch_bounds__(256) void gemm_tf32_kernel(
    const float* __restrict__ A, const float* __restrict__ W, float* __restrict__ C,
    int K, int headmajor, const float* __restrict__ resid) {
    __shared__ uint32_t As[128][36];
    __shared__ uint32_t Ws[128][36];

    const int tid = threadIdx.x;
    const int lane = tid & 31, warp = tid >> 5;
    const int wm = warp >> 1, wn = warp & 1;
    const int rm = wm * 32, cn = wn * 64;
    const int m0 = blockIdx.y * 128, n0 = blockIdx.x * 128;

    float acc[2][8][4];
#pragma unroll
    for (int mt = 0; mt < 2; mt++)
#pragma unroll
        for (int nt = 0; nt < 8; nt++)
#pragma unroll
            for (int i = 0; i < 4; i++) acc[mt][nt][i] = 0.f;

    for (int k0 = 0; k0 < K; k0 += 32) {
#pragma unroll
        for (int p = 0; p < 4; p++) {
            int idx = tid + p * 256;
            int r = idx >> 3, c4 = (idx & 7) * 4;
            float4 av = *(const float4*)(A + (size_t)(m0 + r) * K + k0 + c4);
            float4 wv = *(const float4*)(W + (size_t)(n0 + r) * K + k0 + c4);
            *(uint4*)&As[r][c4] = make_uint4(f2tf32(av.x), f2tf32(av.y), f2tf32(av.z), f2tf32(av.w));
            *(uint4*)&Ws[r][c4] = make_uint4(f2tf32(wv.x), f2tf32(wv.y), f2tf32(wv.z), f2tf32(wv.w));
        }
        __syncthreads();

#pragma unroll
        for (int kk = 0; kk < 4; kk++) {
            const int c0 = kk * 8 + (lane & 3);
            uint32_t a[2][4];
#pragma unroll
            for (int mt = 0; mt < 2; mt++) {
                int r0 = rm + mt * 16 + (lane >> 2);
                a[mt][0] = As[r0][c0];
                a[mt][1] = As[r0 + 8][c0];
                a[mt][2] = As[r0][c0 + 4];
                a[mt][3] = As[r0 + 8][c0 + 4];
            }
            uint32_t b[8][2];
#pragma unroll
            for (int nt = 0; nt < 8; nt++) {
                int rb = cn + nt * 8 + (lane >> 2);
                b[nt][0] = Ws[rb][c0];
                b[nt][1] = Ws[rb][c0 + 4];
            }
#pragma unroll
            for (int mt = 0; mt < 2; mt++)
#pragma unroll
                for (int nt = 0; nt < 8; nt++) mma8(acc[mt][nt], a[mt], b[nt]);
        }
        __syncthreads();
    }

#pragma unroll
    for (int mt = 0; mt < 2; mt++) {
#pragma unroll
        for (int nt = 0; nt < 8; nt++) {
#pragma unroll
            for (int half = 0; half < 2; half++) {
                int row = m0 + rm + mt * 16 + (lane >> 2) + half * 8;
                int col = n0 + cn + nt * 8 + 2 * (lane & 3);
                float v0 = acc[mt][nt][half * 2 + 0];
                float v1 = acc[mt][nt][half * 2 + 1];
                if (resid) {
                    v0 += resid[(size_t)row * DM_ + col];
                    v1 += resid[(size_t)row * DM_ + col + 1];
                }
                if (headmajor) {
                    int b = row >> 11, s = row & (S_ - 1);
                    int h = col >> 6, d = col & (D_ - 1);
                    float2* p = (float2*)&C[((((size_t)(b * H_ + h)) * S_) + s) * D_ + d];
                    *p = make_float2(v0, v1);
                } else {
                    float2* p = (float2*)&C[(size_t)row * DM_ + col];
                    *p = make_float2(v0, v1);
                }
            }
        }
    }
}

// =================================================================================
// Attention pass A (flash): q-tile 128, 8 warps (warp = 16 q-rows x full 64 keys).
// Register-resident online softmax (warp-local shfl reductions); P converted
// C-layout -> A-layout via shuffles, fed directly into PV mma. No score smem.
// =================================================================================
__global__ __launch_bounds__(256, 2) void attn_a_tf32_kernel(
    const float* __restrict__ QH, const float* __restrict__ KH,
    const float* __restrict__ VH, float* __restrict__ AO,
    float* __restrict__ Mv, float* __restrict__ Lv) {
    extern __shared__ uint32_t sm[];
    uint32_t* Qs = sm;                    // [128][68] tf32, pre-scaled by SCALE_
    uint32_t* Ks = Qs + 128 * 68;         // [64 key][68 d] tf32
    uint32_t* Vt = Ks + 64 * 68;          // [64 d][68 key] tf32

    const int tid = threadIdx.x;
    const int lane = tid & 31, warp = tid >> 5;
    const int g = lane >> 2, t = lane & 3;
    const int r0 = warp * 16 + g;         // q row (within tile) for this lane
    const int bh = blockIdx.y;
    const int q0 = blockIdx.x * 128;
    const int srcA = (lane & ~3) | (t >> 1);
    const int srcB = srcA + 2;

    const float* Qp = QH + (size_t)bh * S_ * D_;
    const float* Kp = KH + (size_t)bh * S_ * D_;
    const float* Vp = VH + (size_t)bh * S_ * D_;

    // load Q tile, folding in SCALE_ (exact: x2^-3)
#pragma unroll
    for (int p = 0; p < 8; p++) {
        int idx = tid + p * 256;
        int r = idx >> 4, c4 = (idx & 15) * 4;
        float4 v = *(const float4*)(Qp + (size_t)(q0 + r) * D_ + c4);
        *(uint4*)&Qs[r * 68 + c4] = make_uint4(f2tf32(v.x * SCALE_), f2tf32(v.y * SCALE_),
                                               f2tf32(v.z * SCALE_), f2tf32(v.w * SCALE_));
    }

    float o[8][4];
#pragma unroll
    for (int nt = 0; nt < 8; nt++)
#pragma unroll
        for (int i = 0; i < 4; i++) o[nt][i] = 0.f;

    float rowm0 = -1e30f, rowm1 = -1e30f;
    float rowl0 = 0.f, rowl1 = 0.f;

    for (int kt = 0; kt < S_ / 64; kt++) {
        const int k0 = kt * 64;
        __syncthreads();   // prev iter's PV done with Ks/Vt
        // K tile [64 key][64 d]
#pragma unroll
        for (int p = 0; p < 4; p++) {
            int idx = tid + p * 256;
            int r = idx >> 4, c4 = (idx & 15) * 4;
            float4 kv = *(const float4*)(Kp + (size_t)(k0 + r) * D_ + c4);
            *(uint4*)&Ks[r * 68 + c4] = make_uint4(f2tf32(kv.x), f2tf32(kv.y), f2tf32(kv.z), f2tf32(kv.w));
        }
        // V tile transposed -> Vt[d][key], lane-major key: conflict-free stores
#pragma unroll
        for (int p = 0; p < 4; p++) {
            int idx = tid + p * 256;
            int r = idx & 63, d4 = (idx >> 6) * 4;
            float4 vv = *(const float4*)(Vp + (size_t)(k0 + r) * D_ + d4);
            Vt[(d4 + 0) * 68 + r] = f2tf32(vv.x);
            Vt[(d4 + 1) * 68 + r] = f2tf32(vv.y);
            Vt[(d4 + 2) * 68 + r] = f2tf32(vv.z);
            Vt[(d4 + 3) * 68 + r] = f2tf32(vv.w);
        }
        __syncthreads();

        // ---- S = (Q*scale) @ K^T : sacc[8 key-tiles][4] --------------------------
        float sacc[8][4];
#pragma unroll
        for (int nt = 0; nt < 8; nt++)
#pragma unroll
            for (int i = 0; i < 4; i++) sacc[nt][i] = 0.f;

#pragma unroll
        for (int kk = 0; kk < 8; kk++) {
            const int c0 = kk * 8 + t;
            uint32_t a[4];
            a[0] = Qs[r0 * 68 + c0];
            a[1] = Qs[(r0 + 8) * 68 + c0];
            a[2] = Qs[r0 * 68 + c0 + 4];
            a[3] = Qs[(r0 + 8) * 68 + c0 + 4];
#pragma unroll
            for (int nt = 0; nt < 8; nt++) {
                int rb = nt * 8 + g;
                uint32_t b[2] = {Ks[rb * 68 + c0], Ks[rb * 68 + c0 + 4]};
                mma8(sacc[nt], a, b);
            }
        }

        // ---- register online softmax (rows r0 and r0+8, warp-local) --------------
        float mx0 = -1e30f, mx1 = -1e30f;
#pragma unroll
        for (int nt = 0; nt < 8; nt++) {
            mx0 = fmaxf(mx0, fmaxf(sacc[nt][0], sacc[nt][1]));
            mx1 = fmaxf(mx1, fmaxf(sacc[nt][2], sacc[nt][3]));
        }
        mx0 = fmaxf(mx0, __shfl_xor_sync(0xffffffffu, mx0, 1));
        mx0 = fmaxf(mx0, __shfl_xor_sync(0xffffffffu, mx0, 2));
        mx1 = fmaxf(mx1, __shfl_xor_sync(0xffffffffu, mx1, 1));
        mx1 = fmaxf(mx1, __shfl_xor_sync(0xffffffffu, mx1, 2));

        float mn0 = fmaxf(rowm0, mx0), mn1 = fmaxf(rowm1, mx1);
        float cr0 = __expf(rowm0 - mn0), cr1 = __expf(rowm1 - mn1);
        float ps0 = 0.f, ps1 = 0.f;
#pragma unroll
        for (int nt = 0; nt < 8; nt++) {
            sacc[nt][0] = __expf(sacc[nt][0] - mn0); ps0 += sacc[nt][0];
            sacc[nt][1] = __expf(sacc[nt][1] - mn0); ps0 += sacc[nt][1];
            sacc[nt][2] = __expf(sacc[nt][2] - mn1); ps1 += sacc[nt][2];
            sacc[nt][3] = __expf(sacc[nt][3] - mn1); ps1 += sacc[nt][3];
        }
        ps0 += __shfl_xor_sync(0xffffffffu, ps0, 1);
        ps0 += __shfl_xor_sync(0xffffffffu, ps0, 2);
        ps1 += __shfl_xor_sync(0xffffffffu, ps1, 1);
        ps1 += __shfl_xor_sync(0xffffffffu, ps1, 2);
        rowl0 = rowl0 * cr0 + ps0; rowm0 = mn0;
        rowl1 = rowl1 * cr1 + ps1; rowm1 = mn1;

        // rescale O
#pragma unroll
        for (int nt = 0; nt < 8; nt++) {
            o[nt][0] *= cr0; o[nt][1] *= cr0;
            o[nt][2] *= cr1; o[nt][3] *= cr1;
        }

        // ---- O += P @ V: P C-layout -> A-layout via shuffles ---------------------
#pragma unroll
        for (int kc = 0; kc < 8; kc++) {
            uint32_t p0 = f2tf32(sacc[kc][0]);
            uint32_t p1 = f2tf32(sacc[kc][1]);
            uint32_t p2 = f2tf32(sacc[kc][2]);
            uint32_t p3 = f2tf32(sacc[kc][3]);
            uint32_t pa[4];
            {
                uint32_t u0 = __shfl_sync(0xffffffffu, p0, srcA);
                uint32_t u1 = __shfl_sync(0xffffffffu, p1, srcA);
                pa[0] = (lane & 1) ? u1 : u0;
                u0 = __shfl_sync(0xffffffffu, p2, srcA);
                u1 = __shfl_sync(0xffffffffu, p3, srcA);
                pa[1] = (lane & 1) ? u1 : u0;
                u0 = __shfl_sync(0xffffffffu, p0, srcB);
                u1 = __shfl_sync(0xffffffffu, p1, srcB);
                pa[2] = (lane & 1) ? u1 : u0;
                u0 = __shfl_sync(0xffffffffu, p2, srcB);
                u1 = __shfl_sync(0xffffffffu, p3, srcB);
                pa[3] = (lane & 1) ? u1 : u0;
            }
            const int c0 = kc * 8 + t;
#pragma unroll
            for (int nt = 0; nt < 8; nt++) {
                int rb = nt * 8 + g;
                uint32_t b[2] = {Vt[rb * 68 + c0], Vt[rb * 68 + c0 + 4]};
                mma8(o[nt], pa, b);
            }
        }
    }

    // ---- epilogue -----------------------------------------------------------------
    const int bb = bh >> 4, hh = bh & 15;
    float il0 = 1.f / rowl0, il1 = 1.f / rowl1;
#pragma unroll
    for (int nt = 0; nt < 8; nt++) {
        int col = hh * D_ + nt * 8 + 2 * t;
        size_t base0 = ((size_t)bb * S_ + (q0 + r0)) * DM_ + col;
        size_t base1 = ((size_t)bb * S_ + (q0 + r0 + 8)) * DM_ + col;
        *(float2*)&AO[base0] = make_float2(o[nt][0] * il0, o[nt][1] * il0);
        *(float2*)&AO[base1] = make_float2(o[nt][2] * il1, o[nt][3] * il1);
    }
    if (t == 0) {
        size_t mb = (size_t)bh * S_ + q0 + r0;
        Mv[mb] = rowm0;     Lv[mb] = rowl0;
        Mv[mb + 8] = rowm1; Lv[mb + 8] = rowl1;
    }
}

// =================================================================================
// Attention pass B: recompute scores via mma, write attn = exp(s - m)/l.
// Block: 128 q x 128 k of one (b,h).
// =================================================================================
__global__ __launch_bounds__(256) void attn_b_tf32_kernel(
    const float* __restrict__ QH, const float* __restrict__ KH,
    const float* __restrict__ Mv, const float* __restrict__ Lv,
    float* __restrict__ attn) {
    extern __shared__ uint32_t sm[];
    uint32_t* Qs = sm;               // [128][68]
    uint32_t* Ks = Qs + 128 * 68;    // [128][68]
    float* fm = (float*)(Ks + 128 * 68);
    float* fl = fm + 128;

    const int tid = threadIdx.x;
    const int lane = tid & 31, warp = tid >> 5;
    const int wm = warp >> 1, wn = warp & 1;
    const int rm = wm * 32, cn = wn * 64;
    const int bh = blockIdx.z;
    const int q0 = blockIdx.y * 128;
    const int k0 = blockIdx.x * 128;

    const float* Qp = QH + (size_t)bh * S_ * D_;
    const float* Kp = KH + (size_t)bh * S_ * D_;

#pragma unroll
    for (int p = 0; p < 8; p++) {
        int idx = tid + p * 256;
        int r = idx >> 4, c4 = (idx & 15) * 4;
        float4 qv = *(const float4*)(Qp + (size_t)(q0 + r) * D_ + c4);
        float4 kv = *(const float4*)(Kp + (size_t)(k0 + r) * D_ + c4);
        *(uint4*)&Qs[r * 68 + c4] = make_uint4(f2tf32(qv.x * SCALE_), f2tf32(qv.y * SCALE_),
                                               f2tf32(qv.z * SCALE_), f2tf32(qv.w * SCALE_));
        *(uint4*)&Ks[r * 68 + c4] = make_uint4(f2tf32(kv.x), f2tf32(kv.y), f2tf32(kv.z), f2tf32(kv.w));
    }
    if (tid < 128) {
        fm[tid] = Mv[(size_t)bh * S_ + q0 + tid];
        fl[tid] = 1.f / Lv[(size_t)bh * S_ + q0 + tid];
    }
    __syncthreads();

    float acc[2][8][4];
#pragma unroll
    for (int mt = 0; mt < 2; mt++)
#pragma unroll
        for (int nt = 0; nt < 8; nt++)
#pragma unroll
            for (int i = 0; i < 4; i++) acc[mt][nt][i] = 0.f;

#pragma unroll
    for (int kk = 0; kk < 8; kk++) {
        const int c0 = kk * 8 + (lane & 3);
        uint32_t a[2][4];
#pragma unroll
        for (int mt = 0; mt < 2; mt++) {
            int r0 = rm + mt * 16 + (lane >> 2);
            a[mt][0] = Qs[r0 * 68 + c0];
            a[mt][1] = Qs[(r0 + 8) * 68 + c0];
            a[mt][2] = Qs[r0 * 68 + c0 + 4];
            a[mt][3] = Qs[(r0 + 8) * 68 + c0 + 4];
        }
        uint32_t b[8][2];
#pragma unroll
        for (int nt = 0; nt < 8; nt++) {
            int rb = cn + nt * 8 + (lane >> 2);
            b[nt][0] = Ks[rb * 68 + c0];
            b[nt][1] = Ks[rb * 68 + c0 + 4];
        }
#pragma unroll
        for (int mt = 0; mt < 2; mt++)
#pragma unroll
            for (int nt = 0; nt < 8; nt++) mma8(acc[mt][nt], a[mt], b[nt]);
    }

#pragma unroll
    for (int mt = 0; mt < 2; mt++) {
#pragma unroll
        for (int half = 0; half < 2; half++) {
            int r0 = rm + mt * 16 + (lane >> 2) + half * 8;
            float m = fm[r0], il = fl[r0];
            size_t rowbase = ((size_t)bh * S_ + (q0 + r0)) * S_ + k0;
#pragma unroll
            for (int nt = 0; nt < 8; nt++) {
                int c = cn + nt * 8 + 2 * (lane & 3);
                float2 v;
                v.x = __expf(acc[mt][nt][half * 2 + 0] - m) * il;
                v.y = __expf(acc[mt][nt][half * 2 + 1] - m) * il;
                *(float2*)&attn[rowbase + c] = v;
            }
        }
    }
}

// =================================================================================
// LayerNorm over last dim (1024).
// =================================================================================
__global__ void ln_kernel(const float* __restrict__ FC, const float* __restrict__ gamma,
                          const float* __restrict__ beta, float* __restrict__ out) {
    __shared__ float sbuf[32];
    const int row = blockIdx.x;
    const int tid = threadIdx.x;
    const float* x = FC + (size_t)row * DM_;

    float v[4];
    float s = 0.f;
#pragma unroll
    for (int i = 0; i < 4; i++) { v[i] = x[tid + i * 256]; s += v[i]; }
    {
        int lane = tid & 31, wid = tid >> 5;
        for (int o = 16; o > 0; o >>= 1) s += __shfl_down_sync(0xffffffffu, s, o);
        if (lane == 0) sbuf[wid] = s;
        __syncthreads();
        if (wid == 0) {
            float tt = (lane < 8) ? sbuf[lane] : 0.f;
            for (int o = 4; o > 0; o >>= 1) tt += __shfl_down_sync(0xffffffffu, tt, o);
            if (lane == 0) sbuf[0] = tt;
        }
        __syncthreads();
    }
    float mu = sbuf[0] * (1.f / DM_);
    __syncthreads();

    float s2 = 0.f;
#pragma unroll
    for (int i = 0; i < 4; i++) { float d = v[i] - mu; s2 += d * d; }
    {
        int lane = tid & 31, wid = tid >> 5;
        for (int o = 16; o > 0; o >>= 1) s2 += __shfl_down_sync(0xffffffffu, s2, o);
        if (lane == 0) sbuf[wid] = s2;
        __syncthreads();
        if (wid == 0) {
            float tt = (lane < 8) ? sbuf[lane] : 0.f;
            for (int o = 4; o > 0; o >>= 1) tt += __shfl_down_sync(0xffffffffu, tt, o);
            if (lane == 0) sbuf[0] = tt;
        }
        __syncthreads();
    }
    float inv = rsqrtf(sbuf[0] * (1.f / DM_) + EPS_);

#pragma unroll
    for (int i = 0; i < 4; i++) {
        int c = tid + i * 256;
        out[(size_t)row * DM_ + c] = (v[i] - mu) * inv * gamma[c] + beta[c];
    }
}

// =================================================================================
// Launch
// =================================================================================
#define SMEM_A_BYTES ((128*68 + 64*68 + 64*68) * 4)
#define SMEM_B_BYTES ((128*68 + 128*68 + 2*128) * 4)

extern "C" void kernel_launch(void* const* d_in, const int* in_sizes, int n_in,
                              void* d_out, int out_size) {
    const float* q     = (const float*)d_in[0];
    const float* k     = (const float*)d_in[1];
    const float* v     = (const float*)d_in[2];
    const float* w_q   = (const float*)d_in[3];
    const float* w_k   = (const float*)d_in[4];
    const float* w_v   = (const float*)d_in[5];
    const float* w_fc  = (const float*)d_in[6];
    const float* gamma = (const float*)d_in[7];
    const float* beta  = (const float*)d_in[8];

    float* out  = (float*)d_out;
    float* attn = out + OUT_ELEMS;

    void *pQH, *pKH, *pVH, *pAO, *pFC, *pM, *pL;
    cudaGetSymbolAddress(&pQH, g_QH);
    cudaGetSymbolAddress(&pKH, g_KH);
    cudaGetSymbolAddress(&pVH, g_VH);
    cudaGetSymbolAddress(&pAO, g_AO);
    cudaGetSymbolAddress(&pFC, g_FC);
    cudaGetSymbolAddress(&pM, g_M);
    cudaGetSymbolAddress(&pL, g_L);
    float* QH = (float*)pQH; float* KH = (float*)pKH; float* VH = (float*)pVH;
    float* AO = (float*)pAO; float* FC = (float*)pFC;
    float* Mv = (float*)pM;  float* Lv = (float*)pL;

    cudaFuncSetAttribute(attn_a_tf32_kernel, cudaFuncAttributeMaxDynamicSharedMemorySize, SMEM_A_BYTES);
    cudaFuncSetAttribute(attn_b_tf32_kernel, cudaFuncAttributeMaxDynamicSharedMemorySize, SMEM_B_BYTES);

    dim3 gemm_grid(DM_ / 128, M8_ / 128);   // (8, 64)

    // projections -> head-major [B,H,S,D]
    gemm_tf32_kernel<<<gemm_grid, 256>>>(q, w_q, QH, DM_, 1, nullptr);
    gemm_tf32_kernel<<<gemm_grid, 256>>>(k, w_k, KH, DM_, 1, nullptr);
    gemm_tf32_kernel<<<gemm_grid, 256>>>(v, w_v, VH, DM_, 1, nullptr);

    // pass A: flash attention -> AO + (m, l)
    attn_a_tf32_kernel<<<dim3(S_ / 128, BH_), 256, SMEM_A_BYTES>>>(QH, KH, VH, AO, Mv, Lv);

    // pass B: normalized attention probabilities (second output)
    if ((size_t)out_size >= OUT_ELEMS + ATTN_ELEMS) {
        attn_b_tf32_kernel<<<dim3(S_ / 128, S_ / 128, BH_), 256, SMEM_B_BYTES>>>(QH, KH, Mv, Lv, attn);
    }

    // fc + residual
    gemm_tf32_kernel<<<gemm_grid, 256>>>(AO, w_fc, FC, DM_, 0, q);

    // layernorm
    ln_kernel<<<M8_, 256>>>(FC, gamma, beta, out);
}

// round 7
// speedup vs baseline: 4.2462x; 1.3384x over previous
#include <cuda_runtime.h>
#include <cuda_bf16.h>
#include <math.h>
#include <stdint.h>

// Problem constants
#define B_ 4
#define S_ 2048
#define H_ 16
#define D_ 64
#define DM_ 1024
#define M8_ 8192
#define BH_ 64
#define SCALE_ 0.125f
#define EPS_ 1e-6f

#define OUT_ELEMS   (M8_ * DM_)
#define ATTN_ELEMS  ((size_t)BH_ * S_ * S_)

// ---------------- device scratch -----------------------------------------------
__device__ float g_QH[(size_t)BH_ * S_ * D_];   // [B,H,S,D]
__device__ float g_KH[(size_t)BH_ * S_ * D_];
__device__ float g_VH[(size_t)BH_ * S_ * D_];
__device__ float g_AO[(size_t)M8_ * DM_];       // [B,S,H*D]
__device__ float g_FC[(size_t)M8_ * DM_];
__device__ float g_M[(size_t)BH_ * S_];
__device__ float g_L[(size_t)BH_ * S_];

// ---------------- tf32 helpers ---------------------------------------------------
// cvt.rna (round-to-nearest) is REQUIRED: raw truncation is biased toward zero and
// the bias accumulates coherently over K=64 dots -> attn rel_err 3e-3 (R5 failure).
__device__ __forceinline__ uint32_t f2tf32(float x) {
    uint32_t u;
    asm("cvt.rna.tf32.f32 %0, %1;" : "=r"(u) : "f"(x));
    return u;
}

__device__ __forceinline__ void mma8(float* c, const uint32_t* a, const uint32_t* b) {
    asm volatile(
        "mma.sync.aligned.m16n8k8.row.col.f32.tf32.tf32.f32 "
        "{%0,%1,%2,%3}, {%4,%5,%6,%7}, {%8,%9}, {%0,%1,%2,%3};"
        : "+f"(c[0]), "+f"(c[1]), "+f"(c[2]), "+f"(c[3])
        : "r"(a[0]), "r"(a[1]), "r"(a[2]), "r"(a[3]), "r"(b[0]), "r"(b[1]));
}

// =================================================================================
// tf32 GEMM: C[M,N] = A[M,K] @ W[N,K]^T (+resid). 128x128 tile, BK=32, 256 thr.
// Double-buffered: register prefetch of tile k+1 overlaps compute of tile k.
// rna conversion applied at smem store.
// =================================================================================
#define GEMM_SMEM_BYTES (4 * 128 * 36 * 4)

__global__ __launch_bounds__(256) void gemm_tf32_kernel(
    const float* __restrict__ A, const float* __restrict__ W, float* __restrict__ C,
    int K, int headmajor, const float* __restrict__ resid) {
    extern __shared__ uint32_t dynsm[];
    uint32_t* As = dynsm;              // 2 buffers of [128][36]
    uint32_t* Ws = dynsm + 2 * 4608;   // 2 buffers of [128][36]

    const int tid = threadIdx.x;
    const int lane = tid & 31, warp = tid >> 5;
    const int wm = warp >> 1, wn = warp & 1;
    const int rm = wm * 32, cn = wn * 64;
    const int m0 = blockIdx.y * 128, n0 = blockIdx.x * 128;

    // this thread's 4 load slots (1024 float4 slots per matrix tile)
    const int lr0 = tid >> 3, lr1 = (tid + 256) >> 3, lr2 = (tid + 512) >> 3, lr3 = (tid + 768) >> 3;
    const int lc = (tid & 7) * 4;

    float acc[2][8][4];
#pragma unroll
    for (int mt = 0; mt < 2; mt++)
#pragma unroll
        for (int nt = 0; nt < 8; nt++)
#pragma unroll
            for (int i = 0; i < 4; i++) acc[mt][nt][i] = 0.f;

    const int NT = K >> 5;

    float4 pa0, pa1, pa2, pa3, pw0, pw1, pw2, pw3;
    // prefetch tile 0
    pa0 = *(const float4*)(A + (size_t)(m0 + lr0) * K + lc);
    pa1 = *(const float4*)(A + (size_t)(m0 + lr1) * K + lc);
    pa2 = *(const float4*)(A + (size_t)(m0 + lr2) * K + lc);
    pa3 = *(const float4*)(A + (size_t)(m0 + lr3) * K + lc);
    pw0 = *(const float4*)(W + (size_t)(n0 + lr0) * K + lc);
    pw1 = *(const float4*)(W + (size_t)(n0 + lr1) * K + lc);
    pw2 = *(const float4*)(W + (size_t)(n0 + lr2) * K + lc);
    pw3 = *(const float4*)(W + (size_t)(n0 + lr3) * K + lc);

#define STORE_TILE(buf)                                                                    \
    do {                                                                                   \
        uint32_t* Ab_ = As + (buf) * 4608;                                                 \
        uint32_t* Wb_ = Ws + (buf) * 4608;                                                 \
        *(uint4*)&Ab_[lr0 * 36 + lc] = make_uint4(f2tf32(pa0.x), f2tf32(pa0.y), f2tf32(pa0.z), f2tf32(pa0.w)); \
        *(uint4*)&Ab_[lr1 * 36 + lc] = make_uint4(f2tf32(pa1.x), f2tf32(pa1.y), f2tf32(pa1.z), f2tf32(pa1.w)); \
        *(uint4*)&Ab_[lr2 * 36 + lc] = make_uint4(f2tf32(pa2.x), f2tf32(pa2.y), f2tf32(pa2.z), f2tf32(pa2.w)); \
        *(uint4*)&Ab_[lr3 * 36 + lc] = make_uint4(f2tf32(pa3.x), f2tf32(pa3.y), f2tf32(pa3.z), f2tf32(pa3.w)); \
        *(uint4*)&Wb_[lr0 * 36 + lc] = make_uint4(f2tf32(pw0.x), f2tf32(pw0.y), f2tf32(pw0.z), f2tf32(pw0.w)); \
        *(uint4*)&Wb_[lr1 * 36 + lc] = make_uint4(f2tf32(pw1.x), f2tf32(pw1.y), f2tf32(pw1.z), f2tf32(pw1.w)); \
        *(uint4*)&Wb_[lr2 * 36 + lc] = make_uint4(f2tf32(pw2.x), f2tf32(pw2.y), f2tf32(pw2.z), f2tf32(pw2.w)); \
        *(uint4*)&Wb_[lr3 * 36 + lc] = make_uint4(f2tf32(pw3.x), f2tf32(pw3.y), f2tf32(pw3.z), f2tf32(pw3.w)); \
    } while (0)

    STORE_TILE(0);

    for (int kt = 0; kt < NT; kt++) {
        __syncthreads();   // buf[kt&1] visible; prior readers of buf[(kt+1)&1] done
        if (kt + 1 < NT) {
            const int ko = (kt + 1) * 32;
            pa0 = *(const float4*)(A + (size_t)(m0 + lr0) * K + ko + lc);
            pa1 = *(const float4*)(A + (size_t)(m0 + lr1) * K + ko + lc);
            pa2 = *(const float4*)(A + (size_t)(m0 + lr2) * K + ko + lc);
            pa3 = *(const float4*)(A + (size_t)(m0 + lr3) * K + ko + lc);
            pw0 = *(const float4*)(W + (size_t)(n0 + lr0) * K + ko + lc);
            pw1 = *(const float4*)(W + (size_t)(n0 + lr1) * K + ko + lc);
            pw2 = *(const float4*)(W + (size_t)(n0 + lr2) * K + ko + lc);
            pw3 = *(const float4*)(W + (size_t)(n0 + lr3) * K + ko + lc);
        }

        const uint32_t* Ab = As + (kt & 1) * 4608;
        const uint32_t* Wb = Ws + (kt & 1) * 4608;
#pragma unroll
        for (int kk = 0; kk < 4; kk++) {
            const int c0 = kk * 8 + (lane & 3);
            uint32_t a[2][4];
#pragma unroll
            for (int mt = 0; mt < 2; mt++) {
                int r0 = rm + mt * 16 + (lane >> 2);
                a[mt][0] = Ab[r0 * 36 + c0];
                a[mt][1] = Ab[(r0 + 8) * 36 + c0];
                a[mt][2] = Ab[r0 * 36 + c0 + 4];
                a[mt][3] = Ab[(r0 + 8) * 36 + c0 + 4];
            }
            uint32_t b[8][2];
#pragma unroll
            for (int nt = 0; nt < 8; nt++) {
                int rb = cn + nt * 8 + (lane >> 2);
                b[nt][0] = Wb[rb * 36 + c0];
                b[nt][1] = Wb[rb * 36 + c0 + 4];
            }
#pragma unroll
            for (int mt = 0; mt < 2; mt++)
#pragma unroll
                for (int nt = 0; nt < 8; nt++) mma8(acc[mt][nt], a[mt], b[nt]);
        }

        if (kt + 1 < NT) STORE_TILE((kt + 1) & 1);
    }

#pragma unroll
    for (int mt = 0; mt < 2; mt++) {
#pragma unroll
        for (int nt = 0; nt < 8; nt++) {
#pragma unroll
            for (int half = 0; half < 2; half++) {
                int row = m0 + rm + mt * 16 + (lane >> 2) + half * 8;
                int col = n0 + cn + nt * 8 + 2 * (lane & 3);
                float v0 = acc[mt][nt][half * 2 + 0];
                float v1 = acc[mt][nt][half * 2 + 1];
                if (resid) {
                    v0 += resid[(size_t)row * DM_ + col];
                    v1 += resid[(size_t)row * DM_ + col + 1];
                }
                if (headmajor) {
                    int b = row >> 11, s = row & (S_ - 1);
                    int h = col >> 6, d = col & (D_ - 1);
                    float2* p = (float2*)&C[((((size_t)(b * H_ + h)) * S_) + s) * D_ + d];
                    *p = make_float2(v0, v1);
                } else {
                    float2* p = (float2*)&C[(size_t)row * DM_ + col];
                    *p = make_float2(v0, v1);
                }
            }
        }
    }
#undef STORE_TILE
}

// =================================================================================
// Attention pass A (flash): q-tile 128, 8 warps (warp = 16 q-rows x full 64 keys).
// Register-resident online softmax; P shuffled C->A layout. (R4 numerics, rna.)
// =================================================================================
__global__ __launch_bounds__(256, 2) void attn_a_tf32_kernel(
    const float* __restrict__ QH, const float* __restrict__ KH,
    const float* __restrict__ VH, float* __restrict__ AO,
    float* __restrict__ Mv, float* __restrict__ Lv) {
    extern __shared__ uint32_t sm[];
    uint32_t* Qs = sm;                    // [128][68] tf32, pre-scaled
    uint32_t* Ks = Qs + 128 * 68;         // [64 key][68 d]
    uint32_t* Vt = Ks + 64 * 68;          // [64 d][68 key]

    const int tid = threadIdx.x;
    const int lane = tid & 31, warp = tid >> 5;
    const int g = lane >> 2, t = lane & 3;
    const int r0 = warp * 16 + g;
    const int bh = blockIdx.y;
    const int q0 = blockIdx.x * 128;
    const int srcA = (lane & ~3) | (t >> 1);
    const int srcB = srcA + 2;

    const float* Qp = QH + (size_t)bh * S_ * D_;
    const float* Kp = KH + (size_t)bh * S_ * D_;
    const float* Vp = VH + (size_t)bh * S_ * D_;

#pragma unroll
    for (int p = 0; p < 8; p++) {
        int idx = tid + p * 256;
        int r = idx >> 4, c4 = (idx & 15) * 4;
        float4 v = *(const float4*)(Qp + (size_t)(q0 + r) * D_ + c4);
        *(uint4*)&Qs[r * 68 + c4] = make_uint4(f2tf32(v.x * SCALE_), f2tf32(v.y * SCALE_),
                                               f2tf32(v.z * SCALE_), f2tf32(v.w * SCALE_));
    }

    float o[8][4];
#pragma unroll
    for (int nt = 0; nt < 8; nt++)
#pragma unroll
        for (int i = 0; i < 4; i++) o[nt][i] = 0.f;

    float rowm0 = -1e30f, rowm1 = -1e30f;
    float rowl0 = 0.f, rowl1 = 0.f;

    for (int kt = 0; kt < S_ / 64; kt++) {
        const int k0 = kt * 64;
        __syncthreads();
#pragma unroll
        for (int p = 0; p < 4; p++) {
            int idx = tid + p * 256;
            int r = idx >> 4, c4 = (idx & 15) * 4;
            float4 kv = *(const float4*)(Kp + (size_t)(k0 + r) * D_ + c4);
            *(uint4*)&Ks[r * 68 + c4] = make_uint4(f2tf32(kv.x), f2tf32(kv.y), f2tf32(kv.z), f2tf32(kv.w));
        }
#pragma unroll
        for (int p = 0; p < 4; p++) {
            int idx = tid + p * 256;
            int r = idx & 63, d4 = (idx >> 6) * 4;
            float4 vv = *(const float4*)(Vp + (size_t)(k0 + r) * D_ + d4);
            Vt[(d4 + 0) * 68 + r] = f2tf32(vv.x);
            Vt[(d4 + 1) * 68 + r] = f2tf32(vv.y);
            Vt[(d4 + 2) * 68 + r] = f2tf32(vv.z);
            Vt[(d4 + 3) * 68 + r] = f2tf32(vv.w);
        }
        __syncthreads();

        // ---- S = (Q*scale) @ K^T -------------------------------------------------
        float sacc[8][4];
#pragma unroll
        for (int nt = 0; nt < 8; nt++)
#pragma unroll
            for (int i = 0; i < 4; i++) sacc[nt][i] = 0.f;

#pragma unroll
        for (int kk = 0; kk < 8; kk++) {
            const int c0 = kk * 8 + t;
            uint32_t a[4];
            a[0] = Qs[r0 * 68 + c0];
            a[1] = Qs[(r0 + 8) * 68 + c0];
            a[2] = Qs[r0 * 68 + c0 + 4];
            a[3] = Qs[(r0 + 8) * 68 + c0 + 4];
#pragma unroll
            for (int nt = 0; nt < 8; nt++) {
                int rb = nt * 8 + g;
                uint32_t b[2] = {Ks[rb * 68 + c0], Ks[rb * 68 + c0 + 4]};
                mma8(sacc[nt], a, b);
            }
        }

        // ---- register online softmax --------------------------------------------
        float mx0 = -1e30f, mx1 = -1e30f;
#pragma unroll
        for (int nt = 0; nt < 8; nt++) {
            mx0 = fmaxf(mx0, fmaxf(sacc[nt][0], sacc[nt][1]));
            mx1 = fmaxf(mx1, fmaxf(sacc[nt][2], sacc[nt][3]));
        }
        mx0 = fmaxf(mx0, __shfl_xor_sync(0xffffffffu, mx0, 1));
        mx0 = fmaxf(mx0, __shfl_xor_sync(0xffffffffu, mx0, 2));
        mx1 = fmaxf(mx1, __shfl_xor_sync(0xffffffffu, mx1, 1));
        mx1 = fmaxf(mx1, __shfl_xor_sync(0xffffffffu, mx1, 2));

        float mn0 = fmaxf(rowm0, mx0), mn1 = fmaxf(rowm1, mx1);
        float cr0 = __expf(rowm0 - mn0), cr1 = __expf(rowm1 - mn1);
        float ps0 = 0.f, ps1 = 0.f;
#pragma unroll
        for (int nt = 0; nt < 8; nt++) {
            sacc[nt][0] = __expf(sacc[nt][0] - mn0); ps0 += sacc[nt][0];
            sacc[nt][1] = __expf(sacc[nt][1] - mn0); ps0 += sacc[nt][1];
            sacc[nt][2] = __expf(sacc[nt][2] - mn1); ps1 += sacc[nt][2];
            sacc[nt][3] = __expf(sacc[nt][3] - mn1); ps1 += sacc[nt][3];
        }
        ps0 += __shfl_xor_sync(0xffffffffu, ps0, 1);
        ps0 += __shfl_xor_sync(0xffffffffu, ps0, 2);
        ps1 += __shfl_xor_sync(0xffffffffu, ps1, 1);
        ps1 += __shfl_xor_sync(0xffffffffu, ps1, 2);
        rowl0 = rowl0 * cr0 + ps0; rowm0 = mn0;
        rowl1 = rowl1 * cr1 + ps1; rowm1 = mn1;

#pragma unroll
        for (int nt = 0; nt < 8; nt++) {
            o[nt][0] *= cr0; o[nt][1] *= cr0;
            o[nt][2] *= cr1; o[nt][3] *= cr1;
        }

        // ---- O += P @ V (P shuffled C-layout -> A-layout) ------------------------
#pragma unroll
        for (int kc = 0; kc < 8; kc++) {
            uint32_t p0 = f2tf32(sacc[kc][0]);
            uint32_t p1 = f2tf32(sacc[kc][1]);
            uint32_t p2 = f2tf32(sacc[kc][2]);
            uint32_t p3 = f2tf32(sacc[kc][3]);
            uint32_t pa[4];
            {
                uint32_t u0 = __shfl_sync(0xffffffffu, p0, srcA);
                uint32_t u1 = __shfl_sync(0xffffffffu, p1, srcA);
                pa[0] = (lane & 1) ? u1 : u0;
                u0 = __shfl_sync(0xffffffffu, p2, srcA);
                u1 = __shfl_sync(0xffffffffu, p3, srcA);
                pa[1] = (lane & 1) ? u1 : u0;
                u0 = __shfl_sync(0xffffffffu, p0, srcB);
                u1 = __shfl_sync(0xffffffffu, p1, srcB);
                pa[2] = (lane & 1) ? u1 : u0;
                u0 = __shfl_sync(0xffffffffu, p2, srcB);
                u1 = __shfl_sync(0xffffffffu, p3, srcB);
                pa[3] = (lane & 1) ? u1 : u0;
            }
            const int c0 = kc * 8 + t;
#pragma unroll
            for (int nt = 0; nt < 8; nt++) {
                int rb = nt * 8 + g;
                uint32_t b[2] = {Vt[rb * 68 + c0], Vt[rb * 68 + c0 + 4]};
                mma8(o[nt], pa, b);
            }
        }
    }

    // ---- epilogue -----------------------------------------------------------------
    const int bb = bh >> 4, hh = bh & 15;
    float il0 = 1.f / rowl0, il1 = 1.f / rowl1;
#pragma unroll
    for (int nt = 0; nt < 8; nt++) {
        int col = hh * D_ + nt * 8 + 2 * t;
        size_t base0 = ((size_t)bb * S_ + (q0 + r0)) * DM_ + col;
        size_t base1 = ((size_t)bb * S_ + (q0 + r0 + 8)) * DM_ + col;
        *(float2*)&AO[base0] = make_float2(o[nt][0] * il0, o[nt][1] * il0);
        *(float2*)&AO[base1] = make_float2(o[nt][2] * il1, o[nt][3] * il1);
    }
    if (t == 0) {
        size_t mb = (size_t)bh * S_ + q0 + r0;
        Mv[mb] = rowm0;     Lv[mb] = rowl0;
        Mv[mb + 8] = rowm1; Lv[mb + 8] = rowl1;
    }
}

// =================================================================================
// Attention pass B: recompute scores via mma, write attn = exp(s - m)/l.
// =================================================================================
__global__ __launch_bounds__(256) void attn_b_tf32_kernel(
    const float* __restrict__ QH, const float* __restrict__ KH,
    const float* __restrict__ Mv, const float* __restrict__ Lv,
    float* __restrict__ attn) {
    extern __shared__ uint32_t sm[];
    uint32_t* Qs = sm;               // [128][68]
    uint32_t* Ks = Qs + 128 * 68;    // [128][68]
    float* fm = (float*)(Ks + 128 * 68);
    float* fl = fm + 128;

    const int tid = threadIdx.x;
    const int lane = tid & 31, warp = tid >> 5;
    const int wm = warp >> 1, wn = warp & 1;
    const int rm = wm * 32, cn = wn * 64;
    const int bh = blockIdx.z;
    const int q0 = blockIdx.y * 128;
    const int k0 = blockIdx.x * 128;

    const float* Qp = QH + (size_t)bh * S_ * D_;
    const float* Kp = KH + (size_t)bh * S_ * D_;

#pragma unroll
    for (int p = 0; p < 8; p++) {
        int idx = tid + p * 256;
        int r = idx >> 4, c4 = (idx & 15) * 4;
        float4 qv = *(const float4*)(Qp + (size_t)(q0 + r) * D_ + c4);
        float4 kv = *(const float4*)(Kp + (size_t)(k0 + r) * D_ + c4);
        *(uint4*)&Qs[r * 68 + c4] = make_uint4(f2tf32(qv.x * SCALE_), f2tf32(qv.y * SCALE_),
                                               f2tf32(qv.z * SCALE_), f2tf32(qv.w * SCALE_));
        *(uint4*)&Ks[r * 68 + c4] = make_uint4(f2tf32(kv.x), f2tf32(kv.y), f2tf32(kv.z), f2tf32(kv.w));
    }
    if (tid < 128) {
        fm[tid] = Mv[(size_t)bh * S_ + q0 + tid];
        fl[tid] = 1.f / Lv[(size_t)bh * S_ + q0 + tid];
    }
    __syncthreads();

    float acc[2][8][4];
#pragma unroll
    for (int mt = 0; mt < 2; mt++)
#pragma unroll
        for (int nt = 0; nt < 8; nt++)
#pragma unroll
            for (int i = 0; i < 4; i++) acc[mt][nt][i] = 0.f;

#pragma unroll
    for (int kk = 0; kk < 8; kk++) {
        const int c0 = kk * 8 + (lane & 3);
        uint32_t a[2][4];
#pragma unroll
        for (int mt = 0; mt < 2; mt++) {
            int r0 = rm + mt * 16 + (lane >> 2);
            a[mt][0] = Qs[r0 * 68 + c0];
            a[mt][1] = Qs[(r0 + 8) * 68 + c0];
            a[mt][2] = Qs[r0 * 68 + c0 + 4];
            a[mt][3] = Qs[(r0 + 8) * 68 + c0 + 4];
        }
        uint32_t b[8][2];
#pragma unroll
        for (int nt = 0; nt < 8; nt++) {
            int rb = cn + nt * 8 + (lane >> 2);
            b[nt][0] = Ks[rb * 68 + c0];
            b[nt][1] = Ks[rb * 68 + c0 + 4];
        }
#pragma unroll
        for (int mt = 0; mt < 2; mt++)
#pragma unroll
            for (int nt = 0; nt < 8; nt++) mma8(acc[mt][nt], a[mt], b[nt]);
    }

#pragma unroll
    for (int mt = 0; mt < 2; mt++) {
#pragma unroll
        for (int half = 0; half < 2; half++) {
            int r0 = rm + mt * 16 + (lane >> 2) + half * 8;
            float m = fm[r0], il = fl[r0];
            size_t rowbase = ((size_t)bh * S_ + (q0 + r0)) * S_ + k0;
#pragma unroll
            for (int nt = 0; nt < 8; nt++) {
                int c = cn + nt * 8 + 2 * (lane & 3);
                float2 v;
                v.x = __expf(acc[mt][nt][half * 2 + 0] - m) * il;
                v.y = __expf(acc[mt][nt][half * 2 + 1] - m) * il;
                *(float2*)&attn[rowbase + c] = v;
            }
        }
    }
}

// =================================================================================
// LayerNorm over last dim (1024).
// =================================================================================
__global__ void ln_kernel(const float* __restrict__ FC, const float* __restrict__ gamma,
                          const float* __restrict__ beta, float* __restrict__ out) {
    __shared__ float sbuf[32];
    const int row = blockIdx.x;
    const int tid = threadIdx.x;
    const float* x = FC + (size_t)row * DM_;

    float v[4];
    float s = 0.f;
#pragma unroll
    for (int i = 0; i < 4; i++) { v[i] = x[tid + i * 256]; s += v[i]; }
    {
        int lane = tid & 31, wid = tid >> 5;
        for (int o = 16; o > 0; o >>= 1) s += __shfl_down_sync(0xffffffffu, s, o);
        if (lane == 0) sbuf[wid] = s;
        __syncthreads();
        if (wid == 0) {
            float tt = (lane < 8) ? sbuf[lane] : 0.f;
            for (int o = 4; o > 0; o >>= 1) tt += __shfl_down_sync(0xffffffffu, tt, o);
            if (lane == 0) sbuf[0] = tt;
        }
        __syncthreads();
    }
    float mu = sbuf[0] * (1.f / DM_);
    __syncthreads();

    float s2 = 0.f;
#pragma unroll
    for (int i = 0; i < 4; i++) { float d = v[i] - mu; s2 += d * d; }
    {
        int lane = tid & 31, wid = tid >> 5;
        for (int o = 16; o > 0; o >>= 1) s2 += __shfl_down_sync(0xffffffffu, s2, o);
        if (lane == 0) sbuf[wid] = s2;
        __syncthreads();
        if (wid == 0) {
            float tt = (lane < 8) ? sbuf[lane] : 0.f;
            for (int o = 4; o > 0; o >>= 1) tt += __shfl_down_sync(0xffffffffu, tt, o);
            if (lane == 0) sbuf[0] = tt;
        }
        __syncthreads();
    }
    float inv = rsqrtf(sbuf[0] * (1.f / DM_) + EPS_);

#pragma unroll
    for (int i = 0; i < 4; i++) {
        int c = tid + i * 256;
        out[(size_t)row * DM_ + c] = (v[i] - mu) * inv * gamma[c] + beta[c];
    }
}

// =================================================================================
// Launch — fork/join concurrency inside graph capture.
// =================================================================================
#define SMEM_A_BYTES ((128*68 + 64*68 + 64*68) * 4)
#define SMEM_B_BYTES ((128*68 + 128*68 + 2*128) * 4)

extern "C" void kernel_launch(void* const* d_in, const int* in_sizes, int n_in,
                              void* d_out, int out_size) {
    const float* q     = (const float*)d_in[0];
    const float* k     = (const float*)d_in[1];
    const float* v     = (const float*)d_in[2];
    const float* w_q   = (const float*)d_in[3];
    const float* w_k   = (const float*)d_in[4];
    const float* w_v   = (const float*)d_in[5];
    const float* w_fc  = (const float*)d_in[6];
    const float* gamma = (const float*)d_in[7];
    const float* beta  = (const float*)d_in[8];

    float* out  = (float*)d_out;
    float* attn = out + OUT_ELEMS;

    void *pQH, *pKH, *pVH, *pAO, *pFC, *pM, *pL;
    cudaGetSymbolAddress(&pQH, g_QH);
    cudaGetSymbolAddress(&pKH, g_KH);
    cudaGetSymbolAddress(&pVH, g_VH);
    cudaGetSymbolAddress(&pAO, g_AO);
    cudaGetSymbolAddress(&pFC, g_FC);
    cudaGetSymbolAddress(&pM, g_M);
    cudaGetSymbolAddress(&pL, g_L);
    float* QH = (float*)pQH; float* KH = (float*)pKH; float* VH = (float*)pVH;
    float* AO = (float*)pAO; float* FC = (float*)pFC;
    float* Mv = (float*)pM;  float* Lv = (float*)pL;

    static cudaStream_t s2 = nullptr, s3 = nullptr;
    static cudaEvent_t ev0 = nullptr, ev2, ev3, evA, evB;
    static bool attrs_set = false;
    if (!s2) {
        cudaStreamCreateWithFlags(&s2, cudaStreamNonBlocking);
        cudaStreamCreateWithFlags(&s3, cudaStreamNonBlocking);
        cudaEventCreateWithFlags(&ev0, cudaEventDisableTiming);
        cudaEventCreateWithFlags(&ev2, cudaEventDisableTiming);
        cudaEventCreateWithFlags(&ev3, cudaEventDisableTiming);
        cudaEventCreateWithFlags(&evA, cudaEventDisableTiming);
        cudaEventCreateWithFlags(&evB, cudaEventDisableTiming);
    }
    if (!attrs_set) {
        cudaFuncSetAttribute(gemm_tf32_kernel, cudaFuncAttributeMaxDynamicSharedMemorySize, GEMM_SMEM_BYTES);
        cudaFuncSetAttribute(attn_a_tf32_kernel, cudaFuncAttributeMaxDynamicSharedMemorySize, SMEM_A_BYTES);
        cudaFuncSetAttribute(attn_b_tf32_kernel, cudaFuncAttributeMaxDynamicSharedMemorySize, SMEM_B_BYTES);
        attrs_set = true;
    }

    dim3 gemm_grid(DM_ / 128, M8_ / 128);   // (8, 64)
    const bool want_attn = (size_t)out_size >= OUT_ELEMS + ATTN_ELEMS;

    // fork: projections in parallel
    cudaEventRecord(ev0, 0);
    cudaStreamWaitEvent(s2, ev0, 0);
    cudaStreamWaitEvent(s3, ev0, 0);
    gemm_tf32_kernel<<<gemm_grid, 256, GEMM_SMEM_BYTES, 0>>>(q, w_q, QH, DM_, 1, nullptr);
    gemm_tf32_kernel<<<gemm_grid, 256, GEMM_SMEM_BYTES, s2>>>(k, w_k, KH, DM_, 1, nullptr);
    gemm_tf32_kernel<<<gemm_grid, 256, GEMM_SMEM_BYTES, s3>>>(v, w_v, VH, DM_, 1, nullptr);
    cudaEventRecord(ev2, s2);
    cudaEventRecord(ev3, s3);
    cudaStreamWaitEvent(0, ev2, 0);
    cudaStreamWaitEvent(0, ev3, 0);

    // pass A: flash attention -> AO + (m, l)
    attn_a_tf32_kernel<<<dim3(S_ / 128, BH_), 256, SMEM_A_BYTES, 0>>>(QH, KH, VH, AO, Mv, Lv);

    // fork: attn_b (write-heavy) concurrent with fc+ln (compute-heavy)
    cudaEventRecord(evA, 0);
    if (want_attn) {
        cudaStreamWaitEvent(s2, evA, 0);
        attn_b_tf32_kernel<<<dim3(S_ / 128, S_ / 128, BH_), 256, SMEM_B_BYTES, s2>>>(QH, KH, Mv, Lv, attn);
        cudaEventRecord(evB, s2);
    }

    gemm_tf32_kernel<<<gemm_grid, 256, GEMM_SMEM_BYTES, 0>>>(AO, w_fc, FC, DM_, 0, q);
    ln_kernel<<<M8_, 256, 0, 0>>>(FC, gamma, beta, out);

    if (want_attn) {
        cudaStreamWaitEvent(0, evB, 0);   // join before returning to harness
    }
}